// round 12
// baseline (speedup 1.0000x reference)
#include <cuda_runtime.h>
#include <cuda_fp16.h>
#include <cstdint>

#define NB 4096
#define NC 64
#define DD 32
#define KK 1024   // H1*H2
#define NSTAGE 2

// ---------------------------------------------------------------- W fragments
// K matrix pre-converted to fp16, laid out per mma.m16n8k16 A-fragment:
// g_Wf16[ch(64)][mt(4)][lane(32)] = uint4 {a0,a1,a2,a3} (each fp16x2).
// a0=(r, k0|k0+1) a1=(r+8, ..) a2=(r, k0+8|k0+9) a3=(r+8, ..),
// r = 16*mt + lane/4, k0 = 2*(lane%4); global k = 16*ch + klocal.
__device__ __align__(16) uint4 g_Wf16[64 * 4 * 32];

__global__ void wfrag_kernel(const float* __restrict__ K) {
    int idx = blockIdx.x * blockDim.x + threadIdx.x;  // 8192
    int lane = idx & 31, mt = (idx >> 5) & 3, ch = idx >> 7;
    int r0 = 16 * mt + (lane >> 2);
    int k0 = 16 * ch + 2 * (lane & 3);
    uint32_t q[4];
#pragma unroll
    for (int u = 0; u < 4; u++) {
        int r = r0 + (u & 1) * 8;
        int k = k0 + (u >> 1) * 8;
        __half2 h = __floats2half2_rn(K[r * KK + k], K[r * KK + k + 1]);
        q[u] = *(uint32_t*)&h;
    }
    g_Wf16[idx] = make_uint4(q[0], q[1], q[2], q[3]);
}

// ---------------------------------------------------------------- helpers
__device__ __forceinline__ uint32_t smem_u32(const void* p) {
    uint32_t a;
    asm("{ .reg .u64 t; cvta.to.shared.u64 t, %1; cvt.u32.u64 %0, t; }"
        : "=r"(a) : "l"(p));
    return a;
}
__device__ __forceinline__ uint32_t f16x2_of(float hi, float lo) {
    uint32_t r;
    asm("cvt.rn.f16x2.f32 %0, %1, %2;" : "=r"(r) : "f"(hi), "f"(lo));
    return r;
}
__device__ __forceinline__ uint32_t hmul2(uint32_t a, uint32_t b) {
    uint32_t r;
    asm("mul.f16x2 %0, %1, %2;" : "=r"(r) : "r"(a), "r"(b));
    return r;
}
__device__ __forceinline__ void mma_f16(float& c0, float& c1, float& c2, float& c3,
                                        uint32_t a0, uint32_t a1, uint32_t a2,
                                        uint32_t a3, uint32_t b0, uint32_t b1) {
    asm volatile(
        "mma.sync.aligned.m16n8k16.row.col.f32.f16.f16.f32 "
        "{%0,%1,%2,%3}, {%4,%5,%6,%7}, {%8,%9}, {%0,%1,%2,%3};"
        : "+f"(c0), "+f"(c1), "+f"(c2), "+f"(c3)
        : "r"(a0), "r"(a1), "r"(a2), "r"(a3), "r"(b0), "r"(b1));
}
#define CP_ASYNC16(dst, src) \
    asm volatile("cp.async.cg.shared.global [%0], [%1], 16;" \
                 :: "r"(dst), "l"(src) : "memory")
#define CP_COMMIT() asm volatile("cp.async.commit_group;" ::: "memory")
#define CP_WAIT(n)  asm volatile("cp.async.wait_group %0;" :: "n"(n) : "memory")

// ---------------------------------------------------------------- main kernel
// CTA: 256 threads = 8 warps = 8 batches. Warp (bp, mh): bp = w>>1 selects
// batch pair {2bp, 2bp+1}; mh = w&1 selects m-tiles {2mh, 2mh+1}.
// Each warp computes its 2 m-tiles x 32 d for BOTH batches of the pair, so
// every A-fragment (W) load feeds 16 MMAs. W streamed via the per-warp
// decoupled cp.async.cg double buffer (no CTA barriers in the mainloop).
// Per-batch GEMM: OUT[c(64), d(32)] = W[c,k] * Z[k,d], K=1024, fp16 1-pass.
__global__ __launch_bounds__(256, 2)
void cin_mma_kernel(const float* __restrict__ X, const float* __restrict__ Y,
                    float* __restrict__ out_mat, float* __restrict__ out_fin) {
    __shared__ float x_s[8 * KK];                  // 32 KB
    __shared__ uint4 w_s[8][NSTAGE][2][32];        // 16 KB (1 KB per warp-stage)

    const int t = threadIdx.x;
    const int lane = t & 31;
    const int w = t >> 5;
    const int bp = w >> 1;            // batch pair 0..3
    const int mh = w & 1;             // m-half: m-tiles {2*mh, 2*mh+1}
    const int b0 = blockIdx.x * 8 + bp * 2;
    const int g = lane >> 2;          // row group / d offset
    const int jm = lane & 3;

    // stage x (coalesced float4): 8 batches
    {
        const float4* xg = (const float4*)(X + (size_t)blockIdx.x * 8 * KK);
        float4* xs4 = (float4*)x_s;
#pragma unroll
        for (int rep = 0; rep < 8; rep++) xs4[rep * 256 + t] = xg[rep * 256 + t];
    }
    __syncthreads();

    // y pre-packed f16x2 for both batches. B frag (n8k16 col):
    // b0 <- klocal {2jm,2jm+1}, b1 <- {2jm+8,2jm+9}; j = p*16 + klocal;
    // d = g + 8*nf. y2[bb][nf][2p+r].
    uint32_t y2[2][4][4];
#pragma unroll
    for (int bb = 0; bb < 2; bb++) {
        const float* yb = Y + (size_t)(b0 + bb) * KK;
#pragma unroll
        for (int nf = 0; nf < 4; nf++) {
            int d = g + 8 * nf;
#pragma unroll
            for (int p = 0; p < 2; p++) {
                y2[bb][nf][2 * p] =
                    f16x2_of(yb[(16 * p + 2 * jm + 1) * 32 + d],
                             yb[(16 * p + 2 * jm) * 32 + d]);
                y2[bb][nf][2 * p + 1] =
                    f16x2_of(yb[(16 * p + 8 + 2 * jm + 1) * 32 + d],
                             yb[(16 * p + 8 + 2 * jm) * 32 + d]);
            }
        }
    }

    float acc[2][2][4][4];   // [m][bb][nf][q]
#pragma unroll
    for (int m = 0; m < 2; m++)
#pragma unroll
        for (int bb = 0; bb < 2; bb++)
#pragma unroll
            for (int n = 0; n < 4; n++)
#pragma unroll
                for (int q = 0; q < 4; q++) acc[m][bb][n][q] = 0.0f;

    // W source pointer for this warp/lane; chunk c, mtile m: gw + c*128 + m*32
    const uint4* gw = g_Wf16 + (2 * mh) * 32 + lane;
    const uint32_t ws0 = smem_u32(&w_s[w][0][0][lane]);
    const uint32_t stage_bytes = 2 * 32 * 16;      // 1 KB per stage
    const uint32_t m_bytes = 32 * 16;

    // prologue: prefetch chunks 0 and 1
#pragma unroll
    for (int s = 0; s < NSTAGE; s++) {
        CP_ASYNC16(ws0 + s * stage_bytes, gw + s * 128);
        CP_ASYNC16(ws0 + s * stage_bytes + m_bytes, gw + s * 128 + 32);
        CP_COMMIT();
    }

    const float* xrow0 = x_s + (bp * 2) * KK;
    const float* xrow1 = x_s + (bp * 2 + 1) * KK;

#pragma unroll 2
    for (int ch = 0; ch < 64; ch++) {
        const int st = ch & 1;        // stage; also p-parity (same thing here)
        const int i = ch >> 1;

        CP_WAIT(NSTAGE - 1);          // chunk ch's fragments resident

        // LDS this warp's A fragments for chunk ch (own-lane data only)
        uint4 a0 = w_s[w][st][0][lane];
        uint4 a1 = w_s[w][st][1][lane];

        // B fragments for both batches: bf[bb][nf][r] = f16(xi)*y2[bb][nf][2p+r]
        uint32_t bf[2][4][2];
#pragma unroll
        for (int nf = 0; nf < 4; nf++) {
            const float xi0 = xrow0[i * 32 + g + 8 * nf];
            const uint32_t x20 = f16x2_of(xi0, xi0);
            bf[0][nf][0] = hmul2(x20, y2[0][nf][2 * st]);
            bf[0][nf][1] = hmul2(x20, y2[0][nf][2 * st + 1]);
            const float xi1 = xrow1[i * 32 + g + 8 * nf];
            const uint32_t x21 = f16x2_of(xi1, xi1);
            bf[1][nf][0] = hmul2(x21, y2[1][nf][2 * st]);
            bf[1][nf][1] = hmul2(x21, y2[1][nf][2 * st + 1]);
        }

#pragma unroll
        for (int bb = 0; bb < 2; bb++)
#pragma unroll
            for (int nf = 0; nf < 4; nf++) {
                mma_f16(acc[0][bb][nf][0], acc[0][bb][nf][1],
                        acc[0][bb][nf][2], acc[0][bb][nf][3],
                        a0.x, a0.y, a0.z, a0.w, bf[bb][nf][0], bf[bb][nf][1]);
                mma_f16(acc[1][bb][nf][0], acc[1][bb][nf][1],
                        acc[1][bb][nf][2], acc[1][bb][nf][3],
                        a1.x, a1.y, a1.z, a1.w, bf[bb][nf][0], bf[bb][nf][1]);
            }

        // prefetch chunk ch+NSTAGE into the stage just freed
        if (ch + NSTAGE < 64) {
            CP_ASYNC16(ws0 + st * stage_bytes, gw + (ch + NSTAGE) * 128);
            CP_ASYNC16(ws0 + st * stage_bytes + m_bytes,
                       gw + (ch + NSTAGE) * 128 + 32);
        }
        CP_COMMIT();                  // keep 1 group per chunk (may be empty)
    }

    // ----- epilogue: D frag rows c = 16*(2*mh+m) + g (+8),
    // cols d = 8*nf + 2*jm + {0,1}; per batch bb.
#pragma unroll
    for (int bb = 0; bb < 2; bb++) {
        float* om = out_mat + (size_t)(b0 + bb) * (NC * DD);
        float* fb = out_fin + (size_t)(b0 + bb) * NC;
#pragma unroll
        for (int m = 0; m < 2; m++) {
            const int c0 = 16 * (2 * mh + m) + g;
            float s0 = 0.0f, s1 = 0.0f;
#pragma unroll
            for (int nf = 0; nf < 4; nf++) {
                int d0 = 8 * nf + 2 * jm;
                *(float2*)&om[c0 * DD + d0] =
                    make_float2(acc[m][bb][nf][0], acc[m][bb][nf][1]);
                *(float2*)&om[(c0 + 8) * DD + d0] =
                    make_float2(acc[m][bb][nf][2], acc[m][bb][nf][3]);
                s0 += acc[m][bb][nf][0] + acc[m][bb][nf][1];
                s1 += acc[m][bb][nf][2] + acc[m][bb][nf][3];
            }
            // sum across the quad (lanes sharing g): covers all 32 d
#pragma unroll
            for (int o = 1; o <= 2; o <<= 1) {
                s0 += __shfl_xor_sync(0xffffffffu, s0, o);
                s1 += __shfl_xor_sync(0xffffffffu, s1, o);
            }
            if (jm == 0) { fb[c0] = s0; fb[c0 + 8] = s1; }
        }
    }
}

extern "C" void kernel_launch(void* const* d_in, const int* in_sizes, int n_in,
                              void* d_out, int out_size) {
    const float* X = (const float*)d_in[0];
    const float* Y = (const float*)d_in[1];
    const float* K = (const float*)d_in[2];
    float* om = (float*)d_out;
    float* fin = om + (size_t)NB * NC * DD;

    wfrag_kernel<<<32, 256>>>(K);
    cin_mma_kernel<<<NB / 8, 256>>>(X, Y, om, fin);
}

// round 13
// speedup vs baseline: 1.5546x; 1.5546x over previous
#include <cuda_runtime.h>
#include <cuda_fp16.h>
#include <cstdint>

#define NB 4096
#define NC 64
#define DD 32
#define KK 1024   // H1*H2
#define NSTAGE 4

// ---------------------------------------------------------------- W fragments
// K matrix pre-converted to fp16, laid out per mma.m16n8k16 A-fragment:
// g_Wf16[ch(64)][mt(4)][lane(32)] = uint4 {a0,a1,a2,a3} (each fp16x2).
// a0=(r, k0|k0+1) a1=(r+8, ..) a2=(r, k0+8|k0+9) a3=(r+8, ..),
// r = 16*mt + lane/4, k0 = 2*(lane%4); global k = 16*ch + klocal.
__device__ __align__(16) uint4 g_Wf16[64 * 4 * 32];

__global__ void wfrag_kernel(const float* __restrict__ K) {
    int idx = blockIdx.x * blockDim.x + threadIdx.x;  // 8192
    int lane = idx & 31, mt = (idx >> 5) & 3, ch = idx >> 7;
    int r0 = 16 * mt + (lane >> 2);
    int k0 = 16 * ch + 2 * (lane & 3);
    uint32_t q[4];
#pragma unroll
    for (int u = 0; u < 4; u++) {
        int r = r0 + (u & 1) * 8;
        int k = k0 + (u >> 1) * 8;
        __half2 h = __floats2half2_rn(K[r * KK + k], K[r * KK + k + 1]);
        q[u] = *(uint32_t*)&h;
    }
    g_Wf16[idx] = make_uint4(q[0], q[1], q[2], q[3]);
}

// ---------------------------------------------------------------- helpers
__device__ __forceinline__ uint32_t smem_u32(const void* p) {
    uint32_t a;
    asm("{ .reg .u64 t; cvta.to.shared.u64 t, %1; cvt.u32.u64 %0, t; }"
        : "=r"(a) : "l"(p));
    return a;
}
__device__ __forceinline__ uint32_t f16x2_of(float hi, float lo) {
    uint32_t r;
    asm("cvt.rn.f16x2.f32 %0, %1, %2;" : "=r"(r) : "f"(hi), "f"(lo));
    return r;
}
__device__ __forceinline__ uint32_t hmul2(uint32_t a, uint32_t b) {
    uint32_t r;
    asm("mul.f16x2 %0, %1, %2;" : "=r"(r) : "r"(a), "r"(b));
    return r;
}
__device__ __forceinline__ void mma_f16(float& c0, float& c1, float& c2, float& c3,
                                        uint32_t a0, uint32_t a1, uint32_t a2,
                                        uint32_t a3, uint32_t b0, uint32_t b1) {
    asm volatile(
        "mma.sync.aligned.m16n8k16.row.col.f32.f16.f16.f32 "
        "{%0,%1,%2,%3}, {%4,%5,%6,%7}, {%8,%9}, {%0,%1,%2,%3};"
        : "+f"(c0), "+f"(c1), "+f"(c2), "+f"(c3)
        : "r"(a0), "r"(a1), "r"(a2), "r"(a3), "r"(b0), "r"(b1));
}
#define CP_ASYNC16(dst, src) \
    asm volatile("cp.async.cg.shared.global [%0], [%1], 16;" \
                 :: "r"(dst), "l"(src) : "memory")
#define CP_COMMIT() asm volatile("cp.async.commit_group;" ::: "memory")
#define CP_WAIT(n)  asm volatile("cp.async.wait_group %0;" :: "n"(n) : "memory")

// ---------------------------------------------------------------- main kernel
// CTA: 256 threads = 8 warps = 4 batches; 2 warps per batch (m-split):
// warp (w&1) covers m-tiles {2*(w&1), 2*(w&1)+1} for all 32 d-columns.
// Per-batch GEMM: OUT[c(64), d(32)] = W[c,k] * Z[k,d], K=1024, fp16 1-pass.
// W streamed via per-warp cp.async.cg 4-stage ring: prefetch distance 3
// iterations (~350+ cyc) covers L2 latency (~260 cyc), unlike the old
// 2-stage version whose CP_WAIT exposed ~100+ cyc per chunk. No CTA
// barriers in the mainloop; warps stay fully decoupled.
// x is staged in SMEM as fp16 (numerically identical: xi was already
// rounded to fp16 before the HMUL2 B-build).
__global__ __launch_bounds__(256, 3)
void cin_mma_kernel(const float* __restrict__ X, const float* __restrict__ Y,
                    float* __restrict__ out_mat, float* __restrict__ out_fin) {
    __shared__ unsigned short x_sh[4 * KK];        // 8 KB (fp16 bits)
    __shared__ uint4 w_s[8][NSTAGE][2][32];        // 32 KB (2 KB per warp-stage)

    const int t = threadIdx.x;
    const int lane = t & 31;
    const int w = t >> 5;
    const int bl = w >> 1;            // local batch 0..3
    const int mh = w & 1;             // m-half: m-tiles {2*mh, 2*mh+1}
    const int b = blockIdx.x * 4 + bl;
    const int g = lane >> 2;          // row group / d offset
    const int jm = lane & 3;

    // stage x as fp16 (coalesced float4 -> uint2 of f16x2)
    {
        const float4* xg = (const float4*)(X + (size_t)blockIdx.x * 4 * KK);
        uint2* xs2 = (uint2*)x_sh;
#pragma unroll
        for (int rep = 0; rep < 4; rep++) {
            float4 v = xg[rep * 256 + t];
            xs2[rep * 256 + t] = make_uint2(f16x2_of(v.y, v.x),
                                            f16x2_of(v.w, v.z));
        }
    }
    __syncthreads();

    // y pre-packed f16x2. B frag (n8k16 col): b0 <- klocal {2jm, 2jm+1},
    // b1 <- {2jm+8, 2jm+9}; j = p*16 + klocal; d = g + 8*nf.
    const float* yb = Y + (size_t)b * KK;
    uint32_t y2[4][4];
#pragma unroll
    for (int nf = 0; nf < 4; nf++) {
        int d = g + 8 * nf;
#pragma unroll
        for (int p = 0; p < 2; p++) {
            y2[nf][2 * p] = f16x2_of(yb[(16 * p + 2 * jm + 1) * 32 + d],
                                     yb[(16 * p + 2 * jm) * 32 + d]);
            y2[nf][2 * p + 1] = f16x2_of(yb[(16 * p + 8 + 2 * jm + 1) * 32 + d],
                                         yb[(16 * p + 8 + 2 * jm) * 32 + d]);
        }
    }

    float acc[2][4][4];
#pragma unroll
    for (int m = 0; m < 2; m++)
#pragma unroll
        for (int n = 0; n < 4; n++)
#pragma unroll
            for (int q = 0; q < 4; q++) acc[m][n][q] = 0.0f;

    // W source pointer for this warp/lane; chunk c, mtile m: gw + c*128 + m*32
    const uint4* gw = g_Wf16 + (2 * mh) * 32 + lane;
    const uint32_t ws0 = smem_u32(&w_s[w][0][0][lane]);
    const uint32_t stage_bytes = 2 * 32 * 16;      // 1 KB per stage
    const uint32_t m_bytes = 32 * 16;

    // prologue: prefetch chunks 0..NSTAGE-1
#pragma unroll
    for (int s = 0; s < NSTAGE; s++) {
        CP_ASYNC16(ws0 + s * stage_bytes, gw + s * 128);
        CP_ASYNC16(ws0 + s * stage_bytes + m_bytes, gw + s * 128 + 32);
        CP_COMMIT();
    }

    const unsigned short* xrow = x_sh + bl * KK + g;

#pragma unroll 2
    for (int ch = 0; ch < 64; ch++) {
        const int st = ch & (NSTAGE - 1);
        const int p = ch & 1;
        const int i = ch >> 1;

        CP_WAIT(NSTAGE - 1);          // chunk ch resident (3 newer may fly)

        // LDS this warp's A fragments for chunk ch (own-lane data only)
        uint4 a0 = w_s[w][st][0][lane];
        uint4 a1 = w_s[w][st][1][lane];

        // B fragments: bf[nf][r] = f16(xi) * y2[nf][2p+r]   (HMUL2)
        uint32_t bf[4][2];
#pragma unroll
        for (int nf = 0; nf < 4; nf++) {
            const uint32_t xh = (uint32_t)xrow[i * 32 + 8 * nf];
            const uint32_t xi2 = xh * 0x00010001u;   // splat f16 to f16x2
            bf[nf][0] = hmul2(xi2, y2[nf][2 * p]);
            bf[nf][1] = hmul2(xi2, y2[nf][2 * p + 1]);
        }

#pragma unroll
        for (int nf = 0; nf < 4; nf++) {
            mma_f16(acc[0][nf][0], acc[0][nf][1], acc[0][nf][2], acc[0][nf][3],
                    a0.x, a0.y, a0.z, a0.w, bf[nf][0], bf[nf][1]);
            mma_f16(acc[1][nf][0], acc[1][nf][1], acc[1][nf][2], acc[1][nf][3],
                    a1.x, a1.y, a1.z, a1.w, bf[nf][0], bf[nf][1]);
        }

        // prefetch chunk ch+NSTAGE into the stage just freed
        if (ch + NSTAGE < 64) {
            CP_ASYNC16(ws0 + st * stage_bytes, gw + (ch + NSTAGE) * 128);
            CP_ASYNC16(ws0 + st * stage_bytes + m_bytes,
                       gw + (ch + NSTAGE) * 128 + 32);
        }
        CP_COMMIT();                  // keep 1 group per chunk (may be empty)
    }

    // ----- epilogue: D frag rows c = 16*(2*mh+m) + g (+8),
    // cols d = 8*nf + 2*jm + {0,1}. Each warp owns distinct c rows.
    float* om = out_mat + (size_t)b * (NC * DD);
    float* fb = out_fin + (size_t)b * NC;
#pragma unroll
    for (int m = 0; m < 2; m++) {
        const int c0 = 16 * (2 * mh + m) + g;
        float s0 = 0.0f, s1 = 0.0f;
#pragma unroll
        for (int nf = 0; nf < 4; nf++) {
            int d0 = 8 * nf + 2 * jm;
            *(float2*)&om[c0 * DD + d0] =
                make_float2(acc[m][nf][0], acc[m][nf][1]);
            *(float2*)&om[(c0 + 8) * DD + d0] =
                make_float2(acc[m][nf][2], acc[m][nf][3]);
            s0 += acc[m][nf][0] + acc[m][nf][1];
            s1 += acc[m][nf][2] + acc[m][nf][3];
        }
        // sum across the quad (lanes sharing g): covers all 32 d
#pragma unroll
        for (int o = 1; o <= 2; o <<= 1) {
            s0 += __shfl_xor_sync(0xffffffffu, s0, o);
            s1 += __shfl_xor_sync(0xffffffffu, s1, o);
        }
        if (jm == 0) { fb[c0] = s0; fb[c0 + 8] = s1; }
    }
}

extern "C" void kernel_launch(void* const* d_in, const int* in_sizes, int n_in,
                              void* d_out, int out_size) {
    const float* X = (const float*)d_in[0];
    const float* Y = (const float*)d_in[1];
    const float* K = (const float*)d_in[2];
    float* om = (float*)d_out;
    float* fin = om + (size_t)NB * NC * DD;

    wfrag_kernel<<<32, 256>>>(K);
    cin_mma_kernel<<<NB / 4, 256>>>(X, Y, om, fin);
}

// round 14
// speedup vs baseline: 1.6917x; 1.0882x over previous
#include <cuda_runtime.h>
#include <cuda_fp16.h>
#include <cstdint>

#define NB 4096
#define NC 64
#define DD 32
#define KK 1024   // H1*H2

// ---------------------------------------------------------------- W fragments
// K matrix pre-converted to fp16, per mma.m16n8k16 A-fragment:
// g_Wf16[ch(64)][mt(4)][lane(32)] = uint4 {a0,a1,a2,a3} (each fp16x2).
// Padded by 2 chunks so the register prefetch's tail loads stay in-bounds.
__device__ __align__(16) uint4 g_Wf16[66 * 4 * 32];

__global__ void wfrag_kernel(const float* __restrict__ K) {
    int idx = blockIdx.x * blockDim.x + threadIdx.x;  // 8192
    int lane = idx & 31, mt = (idx >> 5) & 3, ch = idx >> 7;
    int r0 = 16 * mt + (lane >> 2);
    int k0 = 16 * ch + 2 * (lane & 3);
    uint32_t q[4];
#pragma unroll
    for (int u = 0; u < 4; u++) {
        int r = r0 + (u & 1) * 8;
        int k = k0 + (u >> 1) * 8;
        __half2 h = __floats2half2_rn(K[r * KK + k], K[r * KK + k + 1]);
        q[u] = *(uint32_t*)&h;
    }
    g_Wf16[idx] = make_uint4(q[0], q[1], q[2], q[3]);
}

// ---------------------------------------------------------------- helpers
__device__ __forceinline__ uint32_t f16x2_of(float hi, float lo) {
    uint32_t r;
    asm("cvt.rn.f16x2.f32 %0, %1, %2;" : "=r"(r) : "f"(hi), "f"(lo));
    return r;
}
__device__ __forceinline__ uint32_t hmul2(uint32_t a, uint32_t b) {
    uint32_t r;
    asm("mul.f16x2 %0, %1, %2;" : "=r"(r) : "r"(a), "r"(b));
    return r;
}
__device__ __forceinline__ void mma_f16(float& c0, float& c1, float& c2, float& c3,
                                        uint32_t a0, uint32_t a1, uint32_t a2,
                                        uint32_t a3, uint32_t b0, uint32_t b1) {
    asm volatile(
        "mma.sync.aligned.m16n8k16.row.col.f32.f16.f16.f32 "
        "{%0,%1,%2,%3}, {%4,%5,%6,%7}, {%8,%9}, {%0,%1,%2,%3};"
        : "+f"(c0), "+f"(c1), "+f"(c2), "+f"(c3)
        : "r"(a0), "r"(a1), "r"(a2), "r"(a3), "r"(b0), "r"(b1));
}

// ---------------------------------------------------------------- main kernel
// CTA: 128 threads = 4 warps = 2 batches; 2 warps per batch (m-split):
// warp (w&1) covers m-tiles {2*(w&1), 2*(w&1)+1} for all 32 d-columns.
// Per-batch GEMM: OUT[c(64), d(32)] = W[c,k] * Z[k,d], K=1024, fp16 1-pass.
// W read by plain LDG.128 (L1-resident: 128 KB fits L1D, warm after the
// SM's first CTA) with a 2-chunk register double buffer covering the hit
// latency. x pre-splatted to f16x2 in SMEM as [i][g][nf] so the per-chunk
// x access is ONE broadcast LDS.128. 5 CTAs/SM (<=102 regs) = 20 warps.
__global__ __launch_bounds__(128, 5)
void cin_mma_kernel(const float* __restrict__ X, const float* __restrict__ Y,
                    float* __restrict__ out_mat, float* __restrict__ out_fin) {
    // x_q[bl][i][g][nf] = splat f16x2 of x[b, i, g + 8*nf]; i padded to 33
    // so the tail prefetch (i=32) stays in-bounds.
    __shared__ uint32_t x_q[2][33][8][4];          // 8448 B

    const int t = threadIdx.x;
    const int lane = t & 31;
    const int w = t >> 5;
    const int bl = w >> 1;            // local batch 0..1
    const int mh = w & 1;             // m-half: m-tiles {2*mh, 2*mh+1}
    const int b = blockIdx.x * 2 + bl;
    const int g = lane >> 2;          // row group / d offset
    const int jm = lane & 3;

    // stage x pre-splatted (each thread: 16 values, coalesced float4 loads)
    {
        const float4* xg = (const float4*)(X + (size_t)blockIdx.x * 2 * KK);
#pragma unroll
        for (int rep = 0; rep < 4; rep++) {
            int idx4 = rep * 128 + t;          // 0..511 float4s
            float4 v = xg[idx4];
            int e0 = idx4 * 4;                 // element index (b_l,i,d)
            int b_l = e0 >> 10;
            int i = (e0 >> 5) & 31;
            int d0 = e0 & 31;
            const float vv[4] = {v.x, v.y, v.z, v.w};
#pragma unroll
            for (int u = 0; u < 4; u++) {
                int d = d0 + u;
                x_q[b_l][i][d & 7][d >> 3] = f16x2_of(vv[u], vv[u]);
            }
        }
    }
    __syncthreads();

    // y pre-packed f16x2. B frag (n8k16 col): b0 <- klocal {2jm, 2jm+1},
    // b1 <- {2jm+8, 2jm+9}; j = p*16 + klocal; d = g + 8*nf.
    const float* yb = Y + (size_t)b * KK;
    uint32_t y2[4][4];
#pragma unroll
    for (int nf = 0; nf < 4; nf++) {
        int d = g + 8 * nf;
#pragma unroll
        for (int p = 0; p < 2; p++) {
            y2[nf][2 * p] = f16x2_of(yb[(16 * p + 2 * jm + 1) * 32 + d],
                                     yb[(16 * p + 2 * jm) * 32 + d]);
            y2[nf][2 * p + 1] = f16x2_of(yb[(16 * p + 8 + 2 * jm + 1) * 32 + d],
                                         yb[(16 * p + 8 + 2 * jm) * 32 + d]);
        }
    }

    float acc[2][4][4];
#pragma unroll
    for (int m = 0; m < 2; m++)
#pragma unroll
        for (int n = 0; n < 4; n++)
#pragma unroll
            for (int q = 0; q < 4; q++) acc[m][n][q] = 0.0f;

    // W source pointer; chunk c, mtile m: gw[c*128 + m*32]
    const uint4* gw = g_Wf16 + (2 * mh) * 32 + lane;
    // x presplat pointer: xq[i*8] = uint4 for (bl, i, g)
    const uint4* xq = (const uint4*)&x_q[bl][0][g][0];

    // register double buffer, prefetch distance 2 chunks
    uint4 abuf[2][2];
    abuf[0][0] = gw[0];   abuf[0][1] = gw[32];
    abuf[1][0] = gw[128]; abuf[1][1] = gw[160];
    uint4 xv = xq[0];     // splatted x for i=0, all 4 nf

#pragma unroll 2
    for (int ch = 0; ch < 64; ch++) {
        const int p = ch & 1;
        const int i = ch >> 1;

        // B fragments: bf[nf][r] = xsplat[nf] * y2[nf][2p+r]   (HMUL2)
        const uint32_t xs[4] = {xv.x, xv.y, xv.z, xv.w};
        uint32_t bf[4][2];
#pragma unroll
        for (int nf = 0; nf < 4; nf++) {
            bf[nf][0] = hmul2(xs[nf], y2[nf][2 * p]);
            bf[nf][1] = hmul2(xs[nf], y2[nf][2 * p + 1]);
        }

#pragma unroll
        for (int nf = 0; nf < 4; nf++) {
            mma_f16(acc[0][nf][0], acc[0][nf][1], acc[0][nf][2], acc[0][nf][3],
                    abuf[p][0].x, abuf[p][0].y, abuf[p][0].z, abuf[p][0].w,
                    bf[nf][0], bf[nf][1]);
            mma_f16(acc[1][nf][0], acc[1][nf][1], acc[1][nf][2], acc[1][nf][3],
                    abuf[p][1].x, abuf[p][1].y, abuf[p][1].z, abuf[p][1].w,
                    bf[nf][0], bf[nf][1]);
        }

        // refill this parity's buffer with chunk ch+2 (padded: always safe)
        abuf[p][0] = gw[(ch + 2) * 128];
        abuf[p][1] = gw[(ch + 2) * 128 + 32];
        if (p == 1) xv = xq[(i + 1) * 8];   // next i's x (padded row 32)
    }

    // ----- epilogue: D frag rows c = 16*(2*mh+m) + g (+8),
    // cols d = 8*nf + 2*jm + {0,1}. Each warp owns distinct c rows.
    float* om = out_mat + (size_t)b * (NC * DD);
    float* fb = out_fin + (size_t)b * NC;
#pragma unroll
    for (int m = 0; m < 2; m++) {
        const int c0 = 16 * (2 * mh + m) + g;
        float s0 = 0.0f, s1 = 0.0f;
#pragma unroll
        for (int nf = 0; nf < 4; nf++) {
            int d0 = 8 * nf + 2 * jm;
            *(float2*)&om[c0 * DD + d0] =
                make_float2(acc[m][nf][0], acc[m][nf][1]);
            *(float2*)&om[(c0 + 8) * DD + d0] =
                make_float2(acc[m][nf][2], acc[m][nf][3]);
            s0 += acc[m][nf][0] + acc[m][nf][1];
            s1 += acc[m][nf][2] + acc[m][nf][3];
        }
        // sum across the quad (lanes sharing g): covers all 32 d
#pragma unroll
        for (int o = 1; o <= 2; o <<= 1) {
            s0 += __shfl_xor_sync(0xffffffffu, s0, o);
            s1 += __shfl_xor_sync(0xffffffffu, s1, o);
        }
        if (jm == 0) { fb[c0] = s0; fb[c0 + 8] = s1; }
    }
}

extern "C" void kernel_launch(void* const* d_in, const int* in_sizes, int n_in,
                              void* d_out, int out_size) {
    const float* X = (const float*)d_in[0];
    const float* Y = (const float*)d_in[1];
    const float* K = (const float*)d_in[2];
    float* om = (float*)d_out;
    float* fin = om + (size_t)NB * NC * DD;

    wfrag_kernel<<<32, 256>>>(K);
    cin_mma_kernel<<<NB / 2, 128>>>(X, Y, om, fin);
}

// round 15
// speedup vs baseline: 1.7614x; 1.0412x over previous
#include <cuda_runtime.h>
#include <cuda_fp16.h>
#include <cstdint>

#define NB 4096
#define NC 64
#define DD 32
#define KK 1024   // H1*H2

// ---------------------------------------------------------------- W fragments
// K matrix pre-converted to fp16, per mma.m16n8k16 A-fragment:
// g_Wf16[ch(64)][mt(4)][lane(32)] = uint4 {a0,a1,a2,a3} (each fp16x2).
// a0=(r, k0|k0+1) a1=(r+8, ..) a2=(r, k0+8|k0+9) a3=(r+8, ..),
// r = 16*mt + lane/4, k0 = 2*(lane%4); global k = 16*ch + klocal.
__device__ __align__(16) uint4 g_Wf16[64 * 4 * 32];

__global__ void wfrag_kernel(const float* __restrict__ K) {
    int idx = blockIdx.x * blockDim.x + threadIdx.x;  // 8192
    int lane = idx & 31, mt = (idx >> 5) & 3, ch = idx >> 7;
    int r0 = 16 * mt + (lane >> 2);
    int k0 = 16 * ch + 2 * (lane & 3);
    uint32_t q[4];
#pragma unroll
    for (int u = 0; u < 4; u++) {
        int r = r0 + (u & 1) * 8;
        int k = k0 + (u >> 1) * 8;
        __half2 h = __floats2half2_rn(K[r * KK + k], K[r * KK + k + 1]);
        q[u] = *(uint32_t*)&h;
    }
    g_Wf16[idx] = make_uint4(q[0], q[1], q[2], q[3]);
}

// ---------------------------------------------------------------- helpers
__device__ __forceinline__ uint32_t f16x2_of(float hi, float lo) {
    uint32_t r;
    asm("cvt.rn.f16x2.f32 %0, %1, %2;" : "=r"(r) : "f"(hi), "f"(lo));
    return r;
}
__device__ __forceinline__ uint32_t hmul2(uint32_t a, uint32_t b) {
    uint32_t r;
    asm("mul.f16x2 %0, %1, %2;" : "=r"(r) : "r"(a), "r"(b));
    return r;
}
__device__ __forceinline__ void mma_f16(float& c0, float& c1, float& c2, float& c3,
                                        uint32_t a0, uint32_t a1, uint32_t a2,
                                        uint32_t a3, uint32_t b0, uint32_t b1) {
    asm volatile(
        "mma.sync.aligned.m16n8k16.row.col.f32.f16.f16.f32 "
        "{%0,%1,%2,%3}, {%4,%5,%6,%7}, {%8,%9}, {%0,%1,%2,%3};"
        : "+f"(c0), "+f"(c1), "+f"(c2), "+f"(c3)
        : "r"(a0), "r"(a1), "r"(a2), "r"(a3), "r"(b0), "r"(b1));
}

// ---------------------------------------------------------------- main kernel
// CTA: 128 threads = 4 warps = 4 batches. ONE warp per batch, covering the
// whole per-batch GEMM OUT[c(64), d(32)] = W[c,k]*Z[k,d] (K=1024, fp16
// single pass). Per k16-chunk each warp does ONE B-build (8 HMUL2, shared
// by all m-tiles) + 4 A-fragment LDG.128 (L1-resident W) -> 16 MMAs:
// tensor burst 120 cyc vs ~40 cyc overhead per chunk. 4 CTAs/SM.
__global__ __launch_bounds__(128, 4)
void cin_mma_kernel(const float* __restrict__ X, const float* __restrict__ Y,
                    float* __restrict__ out_mat, float* __restrict__ out_fin) {
    // x_q[bl][i][g][nf] = splat f16x2 of x[b, i, g + 8*nf]
    __shared__ uint32_t x_q[4][32][8][4];          // 16 KB

    const int t = threadIdx.x;
    const int lane = t & 31;
    const int w = t >> 5;             // local batch 0..3
    const int b = blockIdx.x * 4 + w;
    const int g = lane >> 2;          // row group / d offset
    const int jm = lane & 3;

    // stage x pre-splatted (each thread: 8 float4 loads -> 32 splats)
    {
        const float4* xg = (const float4*)(X + (size_t)blockIdx.x * 4 * KK);
#pragma unroll
        for (int rep = 0; rep < 8; rep++) {
            int idx4 = rep * 128 + t;          // 0..1023 float4s
            float4 v = xg[idx4];
            int e0 = idx4 * 4;                 // element index (b_l,i,d)
            int b_l = e0 >> 10;
            int i = (e0 >> 5) & 31;
            int d0 = e0 & 31;
            const float vv[4] = {v.x, v.y, v.z, v.w};
#pragma unroll
            for (int u = 0; u < 4; u++) {
                int d = d0 + u;
                x_q[b_l][i][d & 7][d >> 3] = f16x2_of(vv[u], vv[u]);
            }
        }
    }
    __syncthreads();

    // y pre-packed f16x2. B frag (n8k16 col): b0 <- klocal {2jm, 2jm+1},
    // b1 <- {2jm+8, 2jm+9}; j = p*16 + klocal; d = g + 8*nf.
    const float* yb = Y + (size_t)b * KK;
    uint32_t y2[4][4];
#pragma unroll
    for (int nf = 0; nf < 4; nf++) {
        int d = g + 8 * nf;
#pragma unroll
        for (int p = 0; p < 2; p++) {
            y2[nf][2 * p] = f16x2_of(yb[(16 * p + 2 * jm + 1) * 32 + d],
                                     yb[(16 * p + 2 * jm) * 32 + d]);
            y2[nf][2 * p + 1] = f16x2_of(yb[(16 * p + 8 + 2 * jm + 1) * 32 + d],
                                         yb[(16 * p + 8 + 2 * jm) * 32 + d]);
        }
    }

    float acc[4][4][4];   // [mt][nf][q]
#pragma unroll
    for (int m = 0; m < 4; m++)
#pragma unroll
        for (int n = 0; n < 4; n++)
#pragma unroll
            for (int q = 0; q < 4; q++) acc[m][n][q] = 0.0f;

    // W pointer: chunk ch, mtile mt -> gw[ch*128 + mt*32]
    const uint4* gw = g_Wf16 + lane;
    const uint4* xq = (const uint4*)&x_q[w][0][g][0];

    uint4 xv = xq[0];

#pragma unroll 2
    for (int ch = 0; ch < 64; ch++) {
        const int p = ch & 1;
        const int i = ch >> 1;

        // A fragments for all 4 m-tiles (fresh regs each iter; ptxas
        // pipelines these L1-hit loads across the unrolled iterations)
        uint4 a0 = gw[ch * 128];
        uint4 a1 = gw[ch * 128 + 32];
        uint4 a2 = gw[ch * 128 + 64];
        uint4 a3 = gw[ch * 128 + 96];

        // ONE B-build for the chunk: bf[nf][r] = xsplat[nf]*y2[nf][2p+r]
        const uint32_t xs[4] = {xv.x, xv.y, xv.z, xv.w};
        uint32_t bf[4][2];
#pragma unroll
        for (int nf = 0; nf < 4; nf++) {
            bf[nf][0] = hmul2(xs[nf], y2[nf][2 * p]);
            bf[nf][1] = hmul2(xs[nf], y2[nf][2 * p + 1]);
        }
        if (p == 1 && i < 31) xv = xq[(i + 1) * 8];   // next i's x

        // 16 MMAs
#pragma unroll
        for (int nf = 0; nf < 4; nf++) {
            mma_f16(acc[0][nf][0], acc[0][nf][1], acc[0][nf][2], acc[0][nf][3],
                    a0.x, a0.y, a0.z, a0.w, bf[nf][0], bf[nf][1]);
            mma_f16(acc[1][nf][0], acc[1][nf][1], acc[1][nf][2], acc[1][nf][3],
                    a1.x, a1.y, a1.z, a1.w, bf[nf][0], bf[nf][1]);
            mma_f16(acc[2][nf][0], acc[2][nf][1], acc[2][nf][2], acc[2][nf][3],
                    a2.x, a2.y, a2.z, a2.w, bf[nf][0], bf[nf][1]);
            mma_f16(acc[3][nf][0], acc[3][nf][1], acc[3][nf][2], acc[3][nf][3],
                    a3.x, a3.y, a3.z, a3.w, bf[nf][0], bf[nf][1]);
        }
    }

    // ----- epilogue: D frag rows c = 16*mt + g (+8),
    // cols d = 8*nf + 2*jm + {0,1}. One warp owns the whole batch.
    float* om = out_mat + (size_t)b * (NC * DD);
    float* fb = out_fin + (size_t)b * NC;
#pragma unroll
    for (int mt = 0; mt < 4; mt++) {
        const int c0 = 16 * mt + g;
        float s0 = 0.0f, s1 = 0.0f;
#pragma unroll
        for (int nf = 0; nf < 4; nf++) {
            int d0 = 8 * nf + 2 * jm;
            *(float2*)&om[c0 * DD + d0] =
                make_float2(acc[mt][nf][0], acc[mt][nf][1]);
            *(float2*)&om[(c0 + 8) * DD + d0] =
                make_float2(acc[mt][nf][2], acc[mt][nf][3]);
            s0 += acc[mt][nf][0] + acc[mt][nf][1];
            s1 += acc[mt][nf][2] + acc[mt][nf][3];
        }
        // sum across the quad (lanes sharing g): covers all 32 d
#pragma unroll
        for (int o = 1; o <= 2; o <<= 1) {
            s0 += __shfl_xor_sync(0xffffffffu, s0, o);
            s1 += __shfl_xor_sync(0xffffffffu, s1, o);
        }
        if (jm == 0) { fb[c0] = s0; fb[c0 + 8] = s1; }
    }
}

extern "C" void kernel_launch(void* const* d_in, const int* in_sizes, int n_in,
                              void* d_out, int out_size) {
    const float* X = (const float*)d_in[0];
    const float* Y = (const float*)d_in[1];
    const float* K = (const float*)d_in[2];
    float* om = (float*)d_out;
    float* fin = om + (size_t)NB * NC * DD;

    wfrag_kernel<<<32, 256>>>(K);
    cin_mma_kernel<<<NB / 4, 128>>>(X, Y, om, fin);
}